// round 12
// baseline (speedup 1.0000x reference)
#include <cuda_runtime.h>
#include <cuda_fp16.h>
#include <math_constants.h>
#include <cstdint>

// ---------------------------------------------------------------------------
// Problem constants
// ---------------------------------------------------------------------------
#define N_ROWS 32768
#define DDIM   128
#define KCODE  1024
#define NDTOT  (N_ROWS * DDIM)   // 4194304
#define MARGIN 1e-3f

// scratch (no cudaMalloc allowed)
__device__ __align__(16) __half g_x_hi[NDTOT];
__device__ __align__(16) __half g_e_hi[KCODE * DDIM];
__device__ float        g_xsq[N_ROWS];
__device__ float        g_esq[KCODE];
__device__ int          g_idx[N_ROWS];
__device__ int          g_refrows[N_ROWS];
__device__ unsigned int g_nref;
__device__ double       g_part[1024];
__device__ unsigned int g_done;

// ---------------------------------------------------------------------------
// helpers
// ---------------------------------------------------------------------------
__device__ __forceinline__ uint32_t smem_to_u32(const void* p) {
    uint32_t a;
    asm("{ .reg .u64 t; cvta.to.shared.u64 t, %1; cvt.u32.u64 %0, t; }"
        : "=r"(a) : "l"(p));
    return a;
}

__device__ __forceinline__ void ldsm4(uint32_t* r, uint32_t addr) {
    asm volatile("ldmatrix.sync.aligned.m8n8.x4.shared.b16 {%0,%1,%2,%3}, [%4];"
                 : "=r"(r[0]), "=r"(r[1]), "=r"(r[2]), "=r"(r[3]) : "r"(addr));
}

__device__ __forceinline__ void mma16816(float* d, const uint32_t* a,
                                         const uint32_t* b) {
    asm volatile(
        "mma.sync.aligned.m16n8k16.row.col.f32.f16.f16.f32 "
        "{%0,%1,%2,%3}, {%4,%5,%6,%7}, {%8,%9}, {%0,%1,%2,%3};"
        : "+f"(d[0]), "+f"(d[1]), "+f"(d[2]), "+f"(d[3])
        : "r"(a[0]), "r"(a[1]), "r"(a[2]), "r"(a[3]), "r"(b[0]), "r"(b[1]));
}

// packed fp32x2 FMA: d = a*b + d (R3-proven exact-dot building block)
__device__ __forceinline__ void fma2(unsigned long long& d,
                                     unsigned long long a,
                                     unsigned long long b) {
    asm("fma.rn.f32x2 %0, %1, %2, %0;" : "+l"(d) : "l"(a), "l"(b));
}

// cp.async a [rows x 128 half] tile into padded smem (row stride 272B)
#define STRB 272
__device__ __forceinline__ void load_tile_pad(uint32_t dst,
                                              const __half* __restrict__ g,
                                              int rows, int t, int nt) {
    for (int c = t; c < rows * 16; c += nt) {
        int r = c >> 4, ch = c & 15;
        uint32_t d = dst + (uint32_t)r * STRB + ch * 16;
        const void* s = (const void*)(g + (size_t)r * 128 + ch * 8);
        asm volatile("cp.async.cg.shared.global [%0], [%1], 16;"
                     :: "r"(d), "l"(s) : "memory");
    }
}

// pass-1 smem layout (bytes):
//   A hi [128x128h pad] @ 0      (34816)
//   B stage s (64 codes hi) @ 34816 + s*17408 (2 stages)
//   esq @ 69632 (4096)
#define SA_HI   0
#define SB      34816
#define SB_STAGE 17408
#define SESQ    69632
#define SMEM_TOTAL 73728   // x2 CTAs = 147456 <= 227KB/SM

// ---------------------------------------------------------------------------
// e_sq (order-insensitive; magnitude ~4e-5 vs d2 ~128) + g_nref reset
// ---------------------------------------------------------------------------
__global__ void esq_kernel(const float* __restrict__ emb) {
    if (blockIdx.x == 0 && threadIdx.x == 0) g_nref = 0;
    int warp = (blockIdx.x * blockDim.x + threadIdx.x) >> 5;
    int lane = threadIdx.x & 31;
    if (warp < KCODE) {
        float4 v = *(const float4*)&emb[(size_t)warp * DDIM + lane * 4];
        float s = v.x * v.x + v.y * v.y + v.z * v.z + v.w * v.w;
        #pragma unroll
        for (int o = 16; o > 0; o >>= 1)
            s += __shfl_xor_sync(0xffffffffu, s, o);
        if (lane == 0) g_esq[warp] = s;
    }
}

// emb -> scaled fp16 (e*512 exact power-of-2)
__global__ void convert_emb_kernel(const float* __restrict__ emb) {
    int i = blockIdx.x * blockDim.x + threadIdx.x;
    if (i < KCODE * DDIM)
        g_e_hi[i] = __float2half_rn(emb[i] * 512.0f);
}

// x -> fp16 + per-row x_sq (serial ascending-d, matches R3)
__global__ __launch_bounds__(256)
void convert_x_kernel(const float* __restrict__ x) {
    __shared__ float xs[64 * 132];
    const int rb = blockIdx.x * 64;
    const float4* xg = (const float4*)(x + (size_t)rb * DDIM);
    for (int t = threadIdx.x; t < 64 * 32; t += 256) {
        int r = t >> 5, c = t & 31;
        *(float4*)&xs[r * 132 + c * 4] = xg[r * 32 + c];
    }
    __syncthreads();
    if (threadIdx.x < 64) {
        const float* row = &xs[threadIdx.x * 132];
        float s = 0.0f;
        #pragma unroll 8
        for (int d = 0; d < DDIM; ++d)
            s = __fadd_rn(s, __fmul_rn(row[d], row[d]));
        g_xsq[rb + threadIdx.x] = s;
    }
    for (int i = threadIdx.x; i < 64 * DDIM; i += 256) {
        int r = i >> 7, c = i & 127;
        g_x_hi[(size_t)(rb + r) * DDIM + c] = __float2half_rn(xs[r * 132 + c]);
    }
}

// ---------------------------------------------------------------------------
// Pass 1: hi-only HMMA approx distances + per-row global TOP-2.
// 256 CTAs x 128 threads, 2 CTAs/SM. CTA = 128 rows x 1024 codes
// (16 N-tiles of 64). Warp owns 32 rows x all 64 cols.
// If top2 gap < MARGIN (or tie), row is queued for exact refine.
// Approx error (missing hl/lh/ll terms + epilogue rounding) <= ~5e-5 << MARGIN.
// ---------------------------------------------------------------------------
__global__ __launch_bounds__(128, 2)
void vq_pass1(float* __restrict__ out)
{
    extern __shared__ __align__(16) char smem[];
    const uint32_t sb = smem_to_u32(smem);
    const int tid  = threadIdx.x;
    const int lane = tid & 31;
    const int wm   = tid >> 5;
    const int gID  = lane >> 2;
    const int tig  = lane & 3;
    const int rbase = blockIdx.x * 128;

    float* esq_s = (float*)(smem + SESQ);
    for (int i = tid; i < KCODE; i += 128) esq_s[i] = g_esq[i];

    // prologue: group0 = A hi + B stage0; group1 = B stage1
    load_tile_pad(sb + SA_HI, g_x_hi + (size_t)rbase * DDIM, 128, tid, 128);
    load_tile_pad(sb + SB,              g_e_hi,             64, tid, 128);
    asm volatile("cp.async.commit_group;" ::: "memory");
    load_tile_pad(sb + SB + SB_STAGE,   g_e_hi + 64 * DDIM, 64, tid, 128);
    asm volatile("cp.async.commit_group;" ::: "memory");

    float xsq[2][2];
    #pragma unroll
    for (int mf = 0; mf < 2; ++mf)
        #pragma unroll
        for (int h = 0; h < 2; ++h)
            xsq[mf][h] = g_xsq[rbase + wm * 32 + mf * 16 + gID + h * 8];

    float bv1[2][2], bv2[2][2];
    int   bk1[2][2];
    #pragma unroll
    for (int mf = 0; mf < 2; ++mf)
        #pragma unroll
        for (int h = 0; h < 2; ++h) {
            bv1[mf][h] = CUDART_INF_F; bv2[mf][h] = CUDART_INF_F; bk1[mf][h] = 0;
        }

    const uint32_t a_off = (uint32_t)((wm * 32 + (lane & 15)) * STRB + (lane >> 4) * 16);
    const uint32_t b_off = (uint32_t)(((lane & 7) + ((lane >> 4) << 3)) * STRB
                                      + ((lane >> 3) & 1) * 16);

    // wait for A (group0), preload all A-hi fragments into regs
    asm volatile("cp.async.wait_group 1;" ::: "memory");
    __syncthreads();
    uint32_t aHr[8][2][4];
    #pragma unroll
    for (int ks = 0; ks < 8; ++ks)
        #pragma unroll
        for (int mf = 0; mf < 2; ++mf)
            ldsm4(aHr[ks][mf], sb + SA_HI + a_off + mf * 4352 + ks * 32);

    for (int it = 0; it < 16; ++it) {
        asm volatile("cp.async.wait_group 1;" ::: "memory");
        __syncthreads();
        const uint32_t bs = sb + SB + (uint32_t)(it & 1) * SB_STAGE;

        float acc[2][8][4];
        #pragma unroll
        for (int mf = 0; mf < 2; ++mf)
            #pragma unroll
            for (int nf = 0; nf < 8; ++nf)
                #pragma unroll
                for (int r = 0; r < 4; ++r) acc[mf][nf][r] = 0.0f;

        // B fragments double-buffered over ks: 4 ldsm4 per ks (64 codes)
        uint32_t bHb[2][4][4];
        #pragma unroll
        for (int p = 0; p < 4; ++p)
            ldsm4(bHb[0][p], bs + b_off + p * 4352);

        #pragma unroll
        for (int ks = 0; ks < 8; ++ks) {
            const int cur = ks & 1, nxt = cur ^ 1;
            if (ks < 7) {
                #pragma unroll
                for (int p = 0; p < 4; ++p)
                    ldsm4(bHb[nxt][p], bs + b_off + p * 4352 + (ks + 1) * 32);
            }
            #pragma unroll
            for (int mf = 0; mf < 2; ++mf)
                #pragma unroll
                for (int p = 0; p < 4; ++p) {
                    mma16816(acc[mf][2 * p],     aHr[ks][mf], &bHb[cur][p][0]);
                    mma16816(acc[mf][2 * p + 1], aHr[ks][mf], &bHb[cur][p][2]);
                }
        }

        // epilogue: d2a = fmaf(acc, -1/256, xsq) + esq ; top-2, k ascending
        #pragma unroll
        for (int mf = 0; mf < 2; ++mf)
            #pragma unroll
            for (int nf = 0; nf < 8; ++nf) {
                const int kb = it * 64 + nf * 8 + 2 * tig;
                const float* a4 = acc[mf][nf];
                #pragma unroll
                for (int h = 0; h < 2; ++h) {
                    #pragma unroll
                    for (int j = 0; j < 2; ++j) {
                        float v = __fadd_rn(
                            __fmaf_rn(a4[h * 2 + j], -0.00390625f, xsq[mf][h]),
                            esq_s[kb + j]);
                        if (v < bv2[mf][h]) {
                            if (v < bv1[mf][h]) {
                                bv2[mf][h] = bv1[mf][h];
                                bv1[mf][h] = v; bk1[mf][h] = kb + j;
                            } else {
                                bv2[mf][h] = v;
                            }
                        }
                    }
                }
            }

        __syncthreads();
        if (it + 2 < 16)
            load_tile_pad(bs, g_e_hi + (size_t)(it + 2) * 64 * DDIM, 64, tid, 128);
        asm volatile("cp.async.commit_group;" ::: "memory");
    }

    // cross-quad merge of (v1,k1,v2): global top-2, first-min preserved
    #pragma unroll
    for (int mf = 0; mf < 2; ++mf)
        #pragma unroll
        for (int h = 0; h < 2; ++h) {
            float v1 = bv1[mf][h], v2 = bv2[mf][h];
            int   k1 = bk1[mf][h];
            #pragma unroll
            for (int o = 1; o <= 2; o <<= 1) {
                float ov1 = __shfl_xor_sync(0xffffffffu, v1, o);
                int   ok1 = __shfl_xor_sync(0xffffffffu, k1, o);
                float ov2 = __shfl_xor_sync(0xffffffffu, v2, o);
                if (ov1 < v1 || (ov1 == v1 && ok1 < k1)) {
                    v2 = fminf(v1, ov2);
                    v1 = ov1; k1 = ok1;
                } else {
                    v2 = fminf(v2, ov1);
                }
            }
            if (tig == 0) {
                int row = rbase + wm * 32 + mf * 16 + gID + h * 8;
                g_idx[row] = k1;
                out[NDTOT + 1 + row] = (float)k1;
                if (v2 - v1 < MARGIN) {
                    unsigned q = atomicAdd(&g_nref, 1u);
                    g_refrows[q] = row;
                }
            }
        }
}

// ---------------------------------------------------------------------------
// Pass 2 refine: exact f32x2 distance (R3-proven pairing & rounding) for
// queued rows over ALL 1024 codes; first-min tie-break; overwrites g_idx/out.
// ---------------------------------------------------------------------------
__global__ __launch_bounds__(256)
void vq_refine(const float* __restrict__ x,
               const float* __restrict__ emb,
               float* __restrict__ out)
{
    __shared__ __align__(16) float xrow[DDIM];
    __shared__ float rv[256];
    __shared__ int   rk[256];
    const int t = threadIdx.x;
    const int n = (int)g_nref;

    for (int e = blockIdx.x; e < n; e += gridDim.x) {
        const int row = g_refrows[e];
        if (t < 32)
            ((float4*)xrow)[t] = ((const float4*)(x + (size_t)row * DDIM))[t];
        __syncthreads();
        const float xsq = g_xsq[row];

        float bv = CUDART_INF_F;
        int   bk = 0x7fffffff;
        #pragma unroll
        for (int j = 0; j < 4; ++j) {
            const int k = t * 4 + j;
            const ulonglong2* er =
                (const ulonglong2*)(emb + (size_t)k * DDIM);
            const ulonglong2* xr = (const ulonglong2*)xrow;
            unsigned long long acc = 0ULL;
            #pragma unroll 4
            for (int c = 0; c < 32; ++c) {
                ulonglong2 xv = xr[c];
                ulonglong2 ev = er[c];
                fma2(acc, xv.x, ev.x);
                fma2(acc, xv.y, ev.y);
            }
            float2 p = *reinterpret_cast<float2*>(&acc);
            float dot = __fadd_rn(p.x, p.y);
            float d2 = __fadd_rn(__fsub_rn(xsq, 2.0f * dot), g_esq[k]);
            if (d2 < bv) { bv = d2; bk = k; }
        }
        rv[t] = bv; rk[t] = bk;
        __syncthreads();
        for (int o = 128; o > 0; o >>= 1) {
            if (t < o) {
                float vo = rv[t + o]; int ko = rk[t + o];
                if (vo < rv[t] || (vo == rv[t] && ko < rk[t])) {
                    rv[t] = vo; rk[t] = ko;
                }
            }
            __syncthreads();
        }
        if (t == 0) {
            g_idx[row] = rk[0];
            out[NDTOT + 1 + row] = (float)rk[0];
        }
        __syncthreads();   // protect xrow/rv/rk reuse next entry
    }
}

// ---------------------------------------------------------------------------
// quantized output (gather) + fp64 MSE, loss finalized by last block
// ---------------------------------------------------------------------------
__global__ __launch_bounds__(256)
void quant_kernel(const float* __restrict__ x,
                  const float* __restrict__ emb,
                  float* __restrict__ out)
{
    __shared__ double sred[256];
    __shared__ bool last;
    const int total4 = NDTOT / 4;  // 1048576
    double s = 0.0;
    for (int p = blockIdx.x * 256 + threadIdx.x; p < total4; p += gridDim.x * 256) {
        int row = p >> 5, d4 = p & 31;
        int k = g_idx[row];
        float4 q  = *(const float4*)&emb[(size_t)k * DDIM + d4 * 4];
        float4 xv = *(const float4*)&x[(size_t)p * 4];
        ((float4*)out)[p] = q;
        float a = q.x - xv.x, b = q.y - xv.y, c = q.z - xv.z, d = q.w - xv.w;
        s += (double)a * a + (double)b * b + (double)c * c + (double)d * d;
    }
    sred[threadIdx.x] = s;
    __syncthreads();
    for (int o = 128; o > 0; o >>= 1) {
        if (threadIdx.x < o) sred[threadIdx.x] += sred[threadIdx.x + o];
        __syncthreads();
    }
    if (threadIdx.x == 0) {
        g_part[blockIdx.x] = sred[0];
        __threadfence();
        unsigned v = atomicAdd(&g_done, 1u);
        last = (v == 1023u);
    }
    __syncthreads();
    if (last) {
        double tsum = 0.0;
        for (int i = threadIdx.x; i < 1024; i += 256) tsum += g_part[i];
        sred[threadIdx.x] = tsum;
        __syncthreads();
        for (int o = 128; o > 0; o >>= 1) {
            if (threadIdx.x < o) sred[threadIdx.x] += sred[threadIdx.x + o];
            __syncthreads();
        }
        if (threadIdx.x == 0) {
            out[NDTOT] = (float)(1.25 * (sred[0] / (double)NDTOT));
            g_done = 0;   // reset for next graph replay
        }
    }
}

// ---------------------------------------------------------------------------
extern "C" void kernel_launch(void* const* d_in, const int* in_sizes, int n_in,
                              void* d_out, int out_size)
{
    const float* x   = (const float*)d_in[0];
    const float* emb = (const float*)d_in[1];
    float* out = (float*)d_out;

    cudaFuncSetAttribute(vq_pass1,
                         cudaFuncAttributeMaxDynamicSharedMemorySize, SMEM_TOTAL);

    esq_kernel<<<KCODE / 8, 256>>>(emb);                       // also resets g_nref
    convert_emb_kernel<<<(KCODE * DDIM + 255) / 256, 256>>>(emb);
    convert_x_kernel<<<N_ROWS / 64, 256>>>(x);
    vq_pass1<<<N_ROWS / 128, 128, SMEM_TOTAL>>>(out);
    vq_refine<<<256, 256>>>(x, emb, out);
    quant_kernel<<<1024, 256>>>(x, emb, out);
}

// round 13
// speedup vs baseline: 9.6846x; 9.6846x over previous
#include <cuda_runtime.h>
#include <cuda_fp16.h>
#include <math_constants.h>
#include <cstdint>

// ---------------------------------------------------------------------------
// Problem constants
// ---------------------------------------------------------------------------
#define N_ROWS 32768
#define DDIM   128
#define KCODE  1024
#define NDTOT  (N_ROWS * DDIM)   // 4194304
#define KEXT   144               // 128 dims + 1 esq-fold dim + 15 zero pad
#define QMARG  0.032f            // 256 * 1.25e-4 (d2-units threshold)

// scratch (no cudaMalloc allowed)
__device__ __align__(16) __half g_x_hi[NDTOT];
__device__ __align__(16) __half g_e_ext[KCODE * KEXT];
__device__ float        g_xsq[N_ROWS];
__device__ float        g_esq[KCODE];
__device__ int          g_idx[N_ROWS];
__device__ int          g_refrows[N_ROWS];
__device__ unsigned int g_nref;
__device__ double       g_part[1024];
__device__ unsigned int g_done;

// ---------------------------------------------------------------------------
// helpers
// ---------------------------------------------------------------------------
__device__ __forceinline__ uint32_t smem_to_u32(const void* p) {
    uint32_t a;
    asm("{ .reg .u64 t; cvta.to.shared.u64 t, %1; cvt.u32.u64 %0, t; }"
        : "=r"(a) : "l"(p));
    return a;
}

__device__ __forceinline__ void ldsm4(uint32_t* r, uint32_t addr) {
    asm volatile("ldmatrix.sync.aligned.m8n8.x4.shared.b16 {%0,%1,%2,%3}, [%4];"
                 : "=r"(r[0]), "=r"(r[1]), "=r"(r[2]), "=r"(r[3]) : "r"(addr));
}

__device__ __forceinline__ void mma16816(float* d, const uint32_t* a,
                                         const uint32_t* b) {
    asm volatile(
        "mma.sync.aligned.m16n8k16.row.col.f32.f16.f16.f32 "
        "{%0,%1,%2,%3}, {%4,%5,%6,%7}, {%8,%9}, {%0,%1,%2,%3};"
        : "+f"(d[0]), "+f"(d[1]), "+f"(d[2]), "+f"(d[3])
        : "r"(a[0]), "r"(a[1]), "r"(a[2]), "r"(a[3]), "r"(b[0]), "r"(b[1]));
}

// packed fp32x2 FMA (R3-proven exact-dot building block)
__device__ __forceinline__ void fma2(unsigned long long& d,
                                     unsigned long long a,
                                     unsigned long long b) {
    asm("fma.rn.f32x2 %0, %1, %2, %0;" : "+l"(d) : "l"(a), "l"(b));
}

// cp.async a [rows x rowlen-half] tile into padded smem
__device__ __forceinline__ void load_tile(uint32_t dst,
                                          const __half* __restrict__ g,
                                          int rows, int chunks, int strb,
                                          int rowlen, int t, int nt) {
    for (int c = t; c < rows * chunks; c += nt) {
        int r = c / chunks, ch = c - r * chunks;
        uint32_t d = dst + (uint32_t)r * strb + ch * 16;
        const void* s = (const void*)(g + (size_t)r * rowlen + ch * 8);
        asm volatile("cp.async.cg.shared.global [%0], [%1], 16;"
                     :: "r"(d), "l"(s) : "memory");
    }
}

// pass-1 smem layout (bytes):
//   A hi [128 x 128h, stride 272] @ 0       (34816)
//   B stage s [64 x 144h, stride 304] @ 34816 + s*19456  (2 stages)
#define STRB_A  272
#define STRB_B  304
#define SA_HI   0
#define SB      34816
#define SB_STAGE 19456
#define SMEM_TOTAL 73728   // x2 CTAs = 147456 <= 227KB/SM

// ---------------------------------------------------------------------------
// e_sq (order-insensitive; magnitude ~4e-5 vs d2 ~128) + g_nref reset
// ---------------------------------------------------------------------------
__global__ void esq_kernel(const float* __restrict__ emb) {
    if (blockIdx.x == 0 && threadIdx.x == 0) g_nref = 0;
    int warp = (blockIdx.x * blockDim.x + threadIdx.x) >> 5;
    int lane = threadIdx.x & 31;
    if (warp < KCODE) {
        float4 v = *(const float4*)&emb[(size_t)warp * DDIM + lane * 4];
        float s = v.x * v.x + v.y * v.y + v.z * v.z + v.w * v.w;
        #pragma unroll
        for (int o = 16; o > 0; o >>= 1)
            s += __shfl_xor_sync(0xffffffffu, s, o);
        if (lane == 0) g_esq[warp] = s;
    }
}

// emb -> extended fp16: cols 0..127 = e*512, col 128 = -256*esq, 129..143 = 0
__global__ void convert_emb_kernel(const float* __restrict__ emb) {
    int i = blockIdx.x * blockDim.x + threadIdx.x;
    if (i < KCODE * KEXT) {
        int k = i / KEXT, col = i - k * KEXT;
        float v = 0.0f;
        if (col < DDIM)       v = emb[k * DDIM + col] * 512.0f;
        else if (col == DDIM) v = -256.0f * g_esq[k];
        g_e_ext[i] = __float2half_rn(v);
    }
}

// x -> fp16 + per-row x_sq (serial ascending-d, matches R3)
__global__ __launch_bounds__(256)
void convert_x_kernel(const float* __restrict__ x) {
    __shared__ float xs[64 * 132];
    const int rb = blockIdx.x * 64;
    const float4* xg = (const float4*)(x + (size_t)rb * DDIM);
    for (int t = threadIdx.x; t < 64 * 32; t += 256) {
        int r = t >> 5, c = t & 31;
        *(float4*)&xs[r * 132 + c * 4] = xg[r * 32 + c];
    }
    __syncthreads();
    if (threadIdx.x < 64) {
        const float* row = &xs[threadIdx.x * 132];
        float s = 0.0f;
        #pragma unroll 8
        for (int d = 0; d < DDIM; ++d)
            s = __fadd_rn(s, __fmul_rn(row[d], row[d]));
        g_xsq[rb + threadIdx.x] = s;
    }
    for (int i = threadIdx.x; i < 64 * DDIM; i += 256) {
        int r = i >> 7, c = i & 127;
        g_x_hi[(size_t)(rb + r) * DDIM + c] = __float2half_rn(xs[r * 132 + c]);
    }
}

// ---------------------------------------------------------------------------
// Pass 1: hi-only HMMA with esq folded into K-dim 128 (x_ext=1, e_ext=-256esq)
// -> acc = 512*dot - 256*esq ; argmin(d2) == argmax(acc). Epilogue is pure
// branchless top-2 max on raw accumulators (no fma, no LDS, no branches).
// 256 CTAs x 128 threads, 2 CTAs/SM; CTA = 128 rows x 16 N-tiles of 64 codes.
// Rows with acc-gap < QMARG (= d2 gap < 1.25e-4) queued for exact refine.
// ---------------------------------------------------------------------------
__global__ __launch_bounds__(128, 2)
void vq_pass1(float* __restrict__ out)
{
    extern __shared__ __align__(16) char smem[];
    const uint32_t sb = smem_to_u32(smem);
    const int tid  = threadIdx.x;
    const int lane = tid & 31;
    const int wm   = tid >> 5;
    const int gID  = lane >> 2;
    const int tig  = lane & 3;
    const int rbase = blockIdx.x * 128;

    // prologue: group0 = A; group1 = B stage0; group2 = B stage1
    load_tile(sb + SA_HI, g_x_hi + (size_t)rbase * DDIM, 128, 16, STRB_A, DDIM, tid, 128);
    asm volatile("cp.async.commit_group;" ::: "memory");
    load_tile(sb + SB,            g_e_ext,             64, 18, STRB_B, KEXT, tid, 128);
    asm volatile("cp.async.commit_group;" ::: "memory");
    load_tile(sb + SB + SB_STAGE, g_e_ext + 64 * KEXT, 64, 18, STRB_B, KEXT, tid, 128);
    asm volatile("cp.async.commit_group;" ::: "memory");

    float m1[2][2], m2[2][2];
    int   k1[2][2];
    #pragma unroll
    for (int mf = 0; mf < 2; ++mf)
        #pragma unroll
        for (int h = 0; h < 2; ++h) {
            m1[mf][h] = -CUDART_INF_F; m2[mf][h] = -CUDART_INF_F; k1[mf][h] = 0;
        }

    const uint32_t a_off = (uint32_t)((wm * 32 + (lane & 15)) * STRB_A + (lane >> 4) * 16);
    const uint32_t b_off = (uint32_t)(((lane & 7) + ((lane >> 4) << 3)) * STRB_B
                                      + ((lane >> 3) & 1) * 16);

    // constant A fragment for the ext k-step: x_ext = [1, 0, ..., 0]
    uint32_t aext[4];
    aext[0] = aext[1] = (tig == 0) ? 0x00003C00u : 0u;
    aext[2] = aext[3] = 0u;

    // wait for A (2 groups still pending), preload A fragments into regs
    asm volatile("cp.async.wait_group 2;" ::: "memory");
    __syncthreads();
    uint32_t aHr[8][2][4];
    #pragma unroll
    for (int ks = 0; ks < 8; ++ks)
        #pragma unroll
        for (int mf = 0; mf < 2; ++mf)
            ldsm4(aHr[ks][mf], sb + SA_HI + a_off + mf * 4352 + ks * 32);

    for (int it = 0; it < 16; ++it) {
        asm volatile("cp.async.wait_group 1;" ::: "memory");
        __syncthreads();
        const uint32_t bs = sb + SB + (uint32_t)(it & 1) * SB_STAGE;

        float acc[2][8][4];
        #pragma unroll
        for (int mf = 0; mf < 2; ++mf)
            #pragma unroll
            for (int nf = 0; nf < 8; ++nf)
                #pragma unroll
                for (int r = 0; r < 4; ++r) acc[mf][nf][r] = 0.0f;

        // B fragments double-buffered over 9 k-steps (4 ldsm4 each: 64 codes)
        uint32_t bHb[2][4][4];
        #pragma unroll
        for (int p = 0; p < 4; ++p)
            ldsm4(bHb[0][p], bs + b_off + p * 4864);

        #pragma unroll
        for (int ks = 0; ks < 9; ++ks) {
            const int cur = ks & 1, nxt = cur ^ 1;
            if (ks < 8) {
                #pragma unroll
                for (int p = 0; p < 4; ++p)
                    ldsm4(bHb[nxt][p], bs + b_off + p * 4864 + (ks + 1) * 32);
            }
            #pragma unroll
            for (int mf = 0; mf < 2; ++mf) {
                const uint32_t* A = (ks < 8) ? aHr[ks][mf] : aext;
                #pragma unroll
                for (int p = 0; p < 4; ++p) {
                    mma16816(acc[mf][2 * p],     A, &bHb[cur][p][0]);
                    mma16816(acc[mf][2 * p + 1], A, &bHb[cur][p][2]);
                }
            }
        }

        // epilogue: branchless top-2 MAX of raw acc; k ascending per thread
        #pragma unroll
        for (int mf = 0; mf < 2; ++mf)
            #pragma unroll
            for (int nf = 0; nf < 8; ++nf) {
                const int kb = it * 64 + nf * 8 + 2 * tig;
                const float* a4 = acc[mf][nf];
                #pragma unroll
                for (int h = 0; h < 2; ++h)
                    #pragma unroll
                    for (int j = 0; j < 2; ++j) {
                        float v = a4[h * 2 + j];
                        bool b1 = v > m1[mf][h];
                        bool b2 = v > m2[mf][h];
                        m2[mf][h] = b1 ? m1[mf][h] : (b2 ? v : m2[mf][h]);
                        k1[mf][h] = b1 ? (kb + j) : k1[mf][h];
                        m1[mf][h] = b1 ? v : m1[mf][h];
                    }
            }

        __syncthreads();   // all warps done reading this B stage
        if (it + 2 < 16)
            load_tile(bs, g_e_ext + (size_t)(it + 2) * 64 * KEXT, 64, 18, STRB_B, KEXT, tid, 128);
        asm volatile("cp.async.commit_group;" ::: "memory");
    }

    // cross-quad merge: global top-2 max with first-k tie preference
    #pragma unroll
    for (int mf = 0; mf < 2; ++mf)
        #pragma unroll
        for (int h = 0; h < 2; ++h) {
            float v1 = m1[mf][h], v2 = m2[mf][h];
            int   kk = k1[mf][h];
            #pragma unroll
            for (int o = 1; o <= 2; o <<= 1) {
                float ov1 = __shfl_xor_sync(0xffffffffu, v1, o);
                int   ok1 = __shfl_xor_sync(0xffffffffu, kk, o);
                float ov2 = __shfl_xor_sync(0xffffffffu, v2, o);
                if (ov1 > v1 || (ov1 == v1 && ok1 < kk)) {
                    v2 = fmaxf(v1, ov2);
                    v1 = ov1; kk = ok1;
                } else {
                    v2 = fmaxf(v2, ov1);
                }
            }
            if (tig == 0) {
                int row = rbase + wm * 32 + mf * 16 + gID + h * 8;
                g_idx[row] = kk;
                out[NDTOT + 1 + row] = (float)kk;
                if (v1 - v2 < QMARG) {
                    unsigned q = atomicAdd(&g_nref, 1u);
                    g_refrows[q] = row;
                }
            }
        }
}

// ---------------------------------------------------------------------------
// Pass 2 refine: exact f32x2 distance (R3-proven pairing & rounding) for
// queued rows over ALL 1024 codes. 16 rows share each emb chunk (smem-staged)
// -> 16x less L2 traffic than per-row scans. First-min tie-break preserved.
// ---------------------------------------------------------------------------
__global__ __launch_bounds__(256)
void vq_refine(const float* __restrict__ x,
               const float* __restrict__ emb,
               float* __restrict__ out)
{
    __shared__ __align__(16) float xs[16][132];
    __shared__ __align__(16) float es[64][132];
    __shared__ float esq_s[KCODE];
    __shared__ float candv[16][16];
    __shared__ int   candk[16][16];
    const int t = threadIdx.x;
    const int row16 = t >> 4;
    const int col16 = t & 15;
    const int n = (int)g_nref;

    for (int i = t; i < KCODE; i += 256) esq_s[i] = g_esq[i];

    for (int g = blockIdx.x; g * 16 < n; g += gridDim.x) {
        __syncthreads();   // xs/es reuse guard across groups
        // gather 16 x-rows (clamped dummy for tail)
        for (int c = t; c < 16 * 32; c += 256) {
            int r = c >> 5, cc = c & 31;
            int e = g * 16 + r;
            int rid = g_refrows[e < n ? e : n - 1];
            *(float4*)&xs[r][cc * 4] = ((const float4*)(x + (size_t)rid * DDIM))[cc];
        }
        const int myrow = g * 16 + row16;
        const int rowid = (myrow < n) ? g_refrows[myrow] : -1;
        const float xsq = (rowid >= 0) ? g_xsq[rowid] : 0.0f;

        float bv = CUDART_INF_F;
        int   bk = 0x7fffffff;
        for (int ch = 0; ch < 16; ++ch) {
            __syncthreads();
            for (int c = t; c < 64 * 32; c += 256) {
                int r = c >> 5, cc = c & 31;
                *(float4*)&es[r][cc * 4] =
                    ((const float4*)(emb + (size_t)(ch * 64 + r) * DDIM))[cc];
            }
            __syncthreads();
            #pragma unroll
            for (int jj = 0; jj < 4; ++jj) {
                const int kl = col16 + jj * 16;
                const int k  = ch * 64 + kl;
                const ulonglong2* er = (const ulonglong2*)es[kl];
                const ulonglong2* xr = (const ulonglong2*)xs[row16];
                unsigned long long acc = 0ULL;
                #pragma unroll 4
                for (int c = 0; c < 32; ++c) {
                    ulonglong2 xv = xr[c];
                    ulonglong2 ev = er[c];
                    fma2(acc, xv.x, ev.x);
                    fma2(acc, xv.y, ev.y);
                }
                float2 p = *reinterpret_cast<float2*>(&acc);
                float dot = __fadd_rn(p.x, p.y);
                float d2 = __fadd_rn(__fsub_rn(xsq, 2.0f * dot), esq_s[k]);
                if (d2 < bv) { bv = d2; bk = k; }
            }
        }
        candv[row16][col16] = bv;
        candk[row16][col16] = bk;
        __syncthreads();
        if (t < 16) {
            float v = candv[t][0];
            int   k = candk[t][0];
            #pragma unroll
            for (int c = 1; c < 16; ++c) {
                float vo = candv[t][c];
                int   ko = candk[t][c];
                if (vo < v || (vo == v && ko < k)) { v = vo; k = ko; }
            }
            int e = g * 16 + t;
            if (e < n) {
                int rid = g_refrows[e];
                g_idx[rid] = k;
                out[NDTOT + 1 + rid] = (float)k;
            }
        }
    }
}

// ---------------------------------------------------------------------------
// quantized output (gather) + fp64 MSE, loss finalized by last block
// ---------------------------------------------------------------------------
__global__ __launch_bounds__(256)
void quant_kernel(const float* __restrict__ x,
                  const float* __restrict__ emb,
                  float* __restrict__ out)
{
    __shared__ double sred[256];
    __shared__ bool last;
    const int total4 = NDTOT / 4;  // 1048576
    double s = 0.0;
    for (int p = blockIdx.x * 256 + threadIdx.x; p < total4; p += gridDim.x * 256) {
        int row = p >> 5, d4 = p & 31;
        int k = g_idx[row];
        float4 q  = *(const float4*)&emb[(size_t)k * DDIM + d4 * 4];
        float4 xv = *(const float4*)&x[(size_t)p * 4];
        ((float4*)out)[p] = q;
        float a = q.x - xv.x, b = q.y - xv.y, c = q.z - xv.z, d = q.w - xv.w;
        s += (double)a * a + (double)b * b + (double)c * c + (double)d * d;
    }
    sred[threadIdx.x] = s;
    __syncthreads();
    for (int o = 128; o > 0; o >>= 1) {
        if (threadIdx.x < o) sred[threadIdx.x] += sred[threadIdx.x + o];
        __syncthreads();
    }
    if (threadIdx.x == 0) {
        g_part[blockIdx.x] = sred[0];
        __threadfence();
        unsigned v = atomicAdd(&g_done, 1u);
        last = (v == 1023u);
    }
    __syncthreads();
    if (last) {
        double tsum = 0.0;
        for (int i = threadIdx.x; i < 1024; i += 256) tsum += g_part[i];
        sred[threadIdx.x] = tsum;
        __syncthreads();
        for (int o = 128; o > 0; o >>= 1) {
            if (threadIdx.x < o) sred[threadIdx.x] += sred[threadIdx.x + o];
            __syncthreads();
        }
        if (threadIdx.x == 0) {
            out[NDTOT] = (float)(1.25 * (sred[0] / (double)NDTOT));
            g_done = 0;   // reset for next graph replay
        }
    }
}

// ---------------------------------------------------------------------------
extern "C" void kernel_launch(void* const* d_in, const int* in_sizes, int n_in,
                              void* d_out, int out_size)
{
    const float* x   = (const float*)d_in[0];
    const float* emb = (const float*)d_in[1];
    float* out = (float*)d_out;

    cudaFuncSetAttribute(vq_pass1,
                         cudaFuncAttributeMaxDynamicSharedMemorySize, SMEM_TOTAL);

    esq_kernel<<<KCODE / 8, 256>>>(emb);                         // resets g_nref
    convert_emb_kernel<<<(KCODE * KEXT + 255) / 256, 256>>>(emb); // needs g_esq
    convert_x_kernel<<<N_ROWS / 64, 256>>>(x);
    vq_pass1<<<N_ROWS / 128, 128, SMEM_TOTAL>>>(out);
    vq_refine<<<256, 256>>>(x, emb, out);
    quant_kernel<<<1024, 256>>>(x, emb, out);
}